// round 11
// baseline (speedup 1.0000x reference)
#include <cuda_runtime.h>

// LearnedBFGSSolver — transpose + single fused kernel (grid 256, 192 thr, 3 CTAs/SM).
// P1: U0/V0 matvecs straight from L2 (H0 + H0T), zero barriers, 1 thread = 1 column.
// P2: 12x12 Grams -> warp-0 scalar recursion -> barrier-free rebuild -> A, Un in SMEM.
// P3: H = H0 + S^T A + Un^T S rank-24 GEMM, 4x8 register tiles, 6 row passes.

#define NN 192
#define TT 12
#define BE 256

typedef unsigned long long u64;

__device__ float g_H0T[NN * NN];

__device__ __forceinline__ u64 fma2(u64 a, u64 b, u64 c) {
    u64 d; asm("fma.rn.f32x2 %0, %1, %2, %3;" : "=l"(d) : "l"(a), "l"(b), "l"(c));
    return d;
}
__device__ __forceinline__ u64 pack2(float lo, float hi) {
    u64 d; asm("mov.b64 %0, {%1, %2};" : "=l"(d) : "f"(lo), "f"(hi));
    return d;
}
__device__ __forceinline__ void unpack2(u64 v, float& lo, float& hi) {
    asm("mov.b64 {%0, %1}, %2;" : "=f"(lo), "=f"(hi) : "l"(v));
}

// ---- SMEM layout (bytes) ----
#define O_SS 0         // float [12][192]
#define O_SY 9216
#define O_SU 18432
#define O_SV 27648
#define O_G1 36864     // float [12][12] x5
#define O_GW 37440
#define O_CU 38016
#define O_CV 38592
#define O_CB 39168
#define O_C1 39744
#define O_C2 39792
#define O_UN 39840     // union: Yp u64[192][8] (12288) | sA+sUn float[12][192]x2 (18432)
#define SMEM_TOTAL (39840 + 18432)

// ---------------- K1: tiled transpose ----------------
__global__ void transpose_kernel(const float* __restrict__ H0g) {
    __shared__ float tile[32][33];
    int bx = blockIdx.x % 6, by = blockIdx.x / 6;
    int x = bx * 32 + threadIdx.x;
    int y = by * 32 + threadIdx.y;
    tile[threadIdx.y][threadIdx.x] = H0g[y * NN + x];
    __syncthreads();
    int xo = by * 32 + threadIdx.x;
    int yo = bx * 32 + threadIdx.y;
    g_H0T[yo * NN + xo] = tile[threadIdx.x][threadIdx.y];
}

// ---------------- K2: fused solver ----------------
__global__ void __launch_bounds__(192, 3)
bfgs_fused(const float* __restrict__ H0g,
           const float* __restrict__ steps,
           const float* __restrict__ dgs,
           float* __restrict__ out)
{
    extern __shared__ char smraw[];
    float* sS  = (float*)(smraw + O_SS);
    float* sY  = (float*)(smraw + O_SY);
    float* sU  = (float*)(smraw + O_SU);
    float* sV  = (float*)(smraw + O_SV);
    float* g1  = (float*)(smraw + O_G1);
    float* gw  = (float*)(smraw + O_GW);
    float* cu  = (float*)(smraw + O_CU);
    float* cv  = (float*)(smraw + O_CV);
    float* cb  = (float*)(smraw + O_CB);
    float* c1s = (float*)(smraw + O_C1);
    float* c2s = (float*)(smraw + O_C2);
    u64*   Yp  = (u64*)  (smraw + O_UN);
    float* sA  = (float*)(smraw + O_UN);
    float* sUn = (float*)(smraw + O_UN + 9216);

    const int tid = threadIdx.x;
    const int be  = blockIdx.x;

    // ---- Load S, Y ----
    for (int idx = tid; idx < TT * NN / 4; idx += 192) {
        int e = idx * 4;
        int k = e / NN, j = e % NN;
        *(float4*)&sS[k * NN + j] = *(const float4*)&steps[(size_t)(k * BE + be) * NN + j];
        *(float4*)&sY[k * NN + j] = *(const float4*)&dgs  [(size_t)(k * BE + be) * NN + j];
    }
    __syncthreads();

    // ---- Pack Y into t-pairs: Yp[j][p] = (Y[2p][j], Y[2p+1][j]) ----
    {
        int j = tid;
        #pragma unroll
        for (int p = 0; p < 6; p++)
            Yp[j * 8 + p] = pack2(sY[(2 * p) * NN + j], sY[(2 * p + 1) * NN + j]);
    }
    __syncthreads();

    // ---- P1: U0 = H0 y_t, V0 = H0^T y_t. thread = column i, barrier-free ----
    {
        const int i = tid;
        u64 aU[6], aV[6];
        #pragma unroll
        for (int p = 0; p < 6; p++) { aU[p] = 0ull; aV[p] = 0ull; }
        const float* __restrict__ pu = g_H0T + i;   // H0T[j][i] = H0[i][j]
        const float* __restrict__ pv = H0g  + i;    // H0 [j][i]
        #pragma unroll 4
        for (int j = 0; j < NN; j++) {
            float hu = __ldg(&pu[j * NN]);
            float hv = __ldg(&pv[j * NN]);
            u64 hu2 = pack2(hu, hu);
            u64 hv2 = pack2(hv, hv);
            ulonglong2 y01 = *(const ulonglong2*)&Yp[j * 8 + 0];
            ulonglong2 y23 = *(const ulonglong2*)&Yp[j * 8 + 2];
            ulonglong2 y45 = *(const ulonglong2*)&Yp[j * 8 + 4];
            u64 yv[6] = {y01.x, y01.y, y23.x, y23.y, y45.x, y45.y};
            #pragma unroll
            for (int p = 0; p < 6; p++) {
                aU[p] = fma2(hu2, yv[p], aU[p]);
                aV[p] = fma2(hv2, yv[p], aV[p]);
            }
        }
        #pragma unroll
        for (int p = 0; p < 6; p++) {
            float lo, hi;
            unpack2(aU[p], lo, hi);
            sU[(2 * p) * NN + i] = lo; sU[(2 * p + 1) * NN + i] = hi;
            unpack2(aV[p], lo, hi);
            sV[(2 * p) * NN + i] = lo; sV[(2 * p + 1) * NN + i] = hi;
        }
    }
    __syncthreads();

    // ---- Grams: G1 = S Y^T, W = V0 Y^T (2x2 cells per thread, 72 threads) ----
    if (tid < 72) {
        int which = tid / 36;
        int cell  = tid % 36;
        int k0 = (cell / 6) * 2, t0 = (cell % 6) * 2;
        const float* P = which ? sV : sS;
        float a00 = 0.f, a01 = 0.f, a10 = 0.f, a11 = 0.f;
        for (int j = 0; j < NN; j += 4) {
            float4 p0 = *(const float4*)&P[k0 * NN + j];
            float4 p1 = *(const float4*)&P[(k0 + 1) * NN + j];
            float4 q0 = *(const float4*)&sY[t0 * NN + j];
            float4 q1 = *(const float4*)&sY[(t0 + 1) * NN + j];
            a00 += p0.x * q0.x + p0.y * q0.y + p0.z * q0.z + p0.w * q0.w;
            a01 += p0.x * q1.x + p0.y * q1.y + p0.z * q1.z + p0.w * q1.w;
            a10 += p1.x * q0.x + p1.y * q0.y + p1.z * q0.z + p1.w * q0.w;
            a11 += p1.x * q1.x + p1.y * q1.y + p1.z * q1.z + p1.w * q1.w;
        }
        float* G = which ? gw : g1;
        G[k0 * TT + t0] = a00;       G[k0 * TT + t0 + 1] = a01;
        G[(k0 + 1) * TT + t0] = a10; G[(k0 + 1) * TT + t0 + 1] = a11;
    }
    __syncthreads();

    // ---- Warp-0 scalar recursion, lane = column t ----
    if (tid < 32) {
        const int t = (tid < TT) ? tid : (TT - 1);
        float G1c[TT], Wc[TT], Wr[TT];
        float d2c[TT], d3c[TT];
        float c1v[TT], c2v[TT];
        float cuL[TT], cvL[TT], bL[TT];
        #pragma unroll
        for (int m = 0; m < TT; m++) {
            G1c[m] = g1[m * TT + t];
            Wc[m]  = gw[m * TT + t];
            Wr[m]  = gw[t * TT + m];
            cuL[m] = 0.f; cvL[m] = 0.f; bL[m] = 0.f;
        }
        #pragma unroll
        for (int k = 0; k < TT; k++) {
            if (k > 0) {
                const int m = k - 1;
                cuL[m] = c1v[m] * G1c[m] - c2v[m] * d2c[m];
                cvL[m] = c1v[m] * G1c[m] - c2v[m] * d3c[m];
                bL[m]  = -c2v[m] * G1c[m];
            }
            float x2 = Wc[k], x3 = Wr[k];
            #pragma unroll
            for (int m = 0; m < TT - 1; m++) {
                if (m < k) {
                    float cvk = __shfl_sync(0xFFFFFFFFu, cvL[m], k);
                    float cuk = __shfl_sync(0xFFFFFFFFu, cuL[m], k);
                    float bk  = __shfl_sync(0xFFFFFFFFu, bL[m],  k);
                    x2 += cvk * G1c[m] + bk * d2c[m];
                    x3 += cuk * G1c[m] + bk * d3c[m];
                }
            }
            d2c[k] = x2;
            d3c[k] = x3;
            float yHy  = __shfl_sync(0xFFFFFFFFu, x3, k);
            float sdot = __shfl_sync(0xFFFFFFFFu, G1c[k], k);
            float ic = (sdot != 0.0f) ? (1.0f / sdot) : 0.0f;
            c2v[k] = ic;
            c1v[k] = (sdot + yHy) * ic * ic;
        }
        if (tid < TT) {
            #pragma unroll
            for (int m = 0; m < TT - 1; m++) {
                cu[m * TT + t] = cuL[m];
                cv[m * TT + t] = cvL[m];
                cb[m * TT + t] = bL[m];
            }
        }
        if (tid == 0) {
            #pragma unroll
            for (int m = 0; m < TT; m++) { c1s[m] = c1v[m]; c2s[m] = c2v[m]; }
        }
    }
    __syncthreads();

    // ---- Per-element rebuild -> A, Un into SMEM (aliases dead Yp) ----
    {
        const int i = tid;
        float s[TT], u[TT], v[TT];
        #pragma unroll
        for (int k = 0; k < TT; k++) {
            s[k] = sS[k * NN + i];
            u[k] = sU[k * NN + i];
            v[k] = sV[k * NN + i];
        }
        // compute into registers first (Yp alias: no smem writes until all reads done)
        float aout[TT], uout[TT];
        #pragma unroll
        for (int t = 0; t < TT; t++) {
            #pragma unroll
            for (int k = 0; k < TT - 1; k++) {
                if (k < t) {
                    float bb = cb[k * TT + t];
                    u[t] += cu[k * TT + t] * s[k] + bb * u[k];
                    v[t] += cv[k * TT + t] * s[k] + bb * v[k];
                }
            }
            float c1 = c1s[t], c2 = c2s[t];
            aout[t] = c1 * s[t] - c2 * v[t];
            uout[t] = -c2 * u[t];
        }
        __syncthreads();   // everyone done reading Yp region? (Yp dead since P1) — order rebuild reads of cu/cv/cb vs writes below is fine; this sync guards nothing else
        #pragma unroll
        for (int t = 0; t < TT; t++) {
            sA [t * NN + i] = aout[t];
            sUn[t * NN + i] = uout[t];
        }
    }
    __syncthreads();

    // ---- P3: H = H0 + S^T A + Un^T S, rank-24. 4x8 tiles, 6 row passes ----
    const int cg = tid >> 3, rg = tid & 7;   // cg 0..23, rg 0..7
    const int c0 = cg * 8;
    float* ob = out + (size_t)be * NN * NN;

    #pragma unroll 1
    for (int rblk = 0; rblk < NN; rblk += 32) {
        const int grow = rblk + rg * 4;
        u64 acc[4][4];
        #pragma unroll
        for (int r = 0; r < 4; r++) {
            ulonglong2 h01 = *(const ulonglong2*)&H0g[(size_t)(grow + r) * NN + c0];
            ulonglong2 h23 = *(const ulonglong2*)&H0g[(size_t)(grow + r) * NN + c0 + 4];
            acc[r][0] = h01.x; acc[r][1] = h01.y; acc[r][2] = h23.x; acc[r][3] = h23.y;
        }
        #pragma unroll
        for (int k = 0; k < TT; k++) {
            ulonglong2 a01 = *(ulonglong2*)&sA[k * NN + c0];
            ulonglong2 a23 = *(ulonglong2*)&sA[k * NN + c0 + 4];
            ulonglong2 s01 = *(ulonglong2*)&sS[k * NN + c0];
            ulonglong2 s23 = *(ulonglong2*)&sS[k * NN + c0 + 4];
            u64 av[4] = {a01.x, a01.y, a23.x, a23.y};
            u64 sv[4] = {s01.x, s01.y, s23.x, s23.y};
            float4 sr = *(float4*)&sS[k * NN + grow];
            float4 ur = *(float4*)&sUn[k * NN + grow];
            float srow[4] = {sr.x, sr.y, sr.z, sr.w};
            float urow[4] = {ur.x, ur.y, ur.z, ur.w};
            #pragma unroll
            for (int r = 0; r < 4; r++) {
                u64 s2 = pack2(srow[r], srow[r]);
                u64 u2 = pack2(urow[r], urow[r]);
                #pragma unroll
                for (int c = 0; c < 4; c++) {
                    acc[r][c] = fma2(s2, av[c], acc[r][c]);
                    acc[r][c] = fma2(u2, sv[c], acc[r][c]);
                }
            }
        }
        #pragma unroll
        for (int r = 0; r < 4; r++) {
            *(ulonglong2*)&ob[(size_t)(grow + r) * NN + c0] =
                make_ulonglong2(acc[r][0], acc[r][1]);
            *(ulonglong2*)&ob[(size_t)(grow + r) * NN + c0 + 4] =
                make_ulonglong2(acc[r][2], acc[r][3]);
        }
    }
}

extern "C" void kernel_launch(void* const* d_in, const int* in_sizes, int n_in,
                              void* d_out, int out_size) {
    const float* H0    = (const float*)d_in[0];   // inv_hessian [192,192]
    const float* steps = (const float*)d_in[1];   // [12,8,32,192]
    const float* dgs   = (const float*)d_in[2];   // [12,8,32,192]
    float* out = (float*)d_out;                   // [8,32,192,192]

    transpose_kernel<<<36, dim3(32, 32)>>>(H0);
    cudaFuncSetAttribute(bfgs_fused,
                         cudaFuncAttributeMaxDynamicSharedMemorySize, SMEM_TOTAL);
    bfgs_fused<<<BE, 192, SMEM_TOTAL>>>(H0, steps, dgs, out);
}

// round 12
// speedup vs baseline: 1.2001x; 1.2001x over previous
#include <cuda_runtime.h>

// LearnedBFGSSolver — 3 GEMM-shaped kernels:
//  kz: [U0|V0] = Y @ [H0^T | H0] as one tiled GEMM. grid 144 (48 row x 3 col
//      blocks of the 3072x192 output), 64x64 tiles, 256 thr. Both H0
//      orientations staged per k-tile (no transpose kernel).
//  ks: per-pair Grams -> 12x12 scalar recursion -> factor vectors A, Un.
//  ke: H = H0 + S^T A + Un^T S rank-24 GEMM, conflict-free layout, grid 768.

#define NN 192
#define TT 12
#define BE 256

typedef unsigned long long u64;

__device__ float g_U0[TT * BE * NN];   // row r = t*BE+be (same order as dgs rows)
__device__ float g_V0[TT * BE * NN];
__device__ float g_A [BE * TT * NN];   // [be][k][j], be-major for ke
__device__ float g_Un[BE * TT * NN];

__device__ __forceinline__ u64 fma2(u64 a, u64 b, u64 c) {
    u64 d; asm("fma.rn.f32x2 %0, %1, %2, %3;" : "=l"(d) : "l"(a), "l"(b), "l"(c));
    return d;
}
__device__ __forceinline__ u64 pack2(float lo, float hi) {
    u64 d; asm("mov.b64 %0, {%1, %2};" : "=l"(d) : "f"(lo), "f"(hi));
    return d;
}
__device__ __forceinline__ void unpack2(u64 v, float& lo, float& hi) {
    asm("mov.b64 {%0, %1}, %2;" : "=f"(lo), "=f"(hi) : "l"(v));
}

// ---------------- K1: kz — fused double GEMM ----------------
// Output U0[r][i] = sum_j Y[r][j] H0[i][j], V0[r][i] = sum_j Y[r][j] H0[j][i].
__global__ void __launch_bounds__(256)
kz_kernel(const float* __restrict__ H0g, const float* __restrict__ dgs)
{
    __shared__ float sYt[32][68];   // sYt[jj][rr] = Y[r0+rr][j0+jj]
    __shared__ float sBu[32][68];   // sBu[jj][ii] = H0[i0+ii][j0+jj]
    __shared__ float sBv[32][68];   // sBv[jj][ii] = H0[j0+jj][i0+ii]
    const int tid = threadIdx.x;
    const int rb = blockIdx.x % 48, cb = blockIdx.x / 48;
    const int r0 = rb * 64, i0 = cb * 64;
    const int cgi = tid & 15;       // column group: cols i0 + cgi*4 .. +3
    const int rgi = tid >> 4;       // row group:    rows r0 + rgi*4 .. +3

    u64 aU[4][2], aV[4][2];
    #pragma unroll
    for (int r = 0; r < 4; r++) {
        aU[r][0] = 0ull; aU[r][1] = 0ull;
        aV[r][0] = 0ull; aV[r][1] = 0ull;
    }

    for (int jt = 0; jt < 6; jt++) {
        const int j0 = jt * 32;
        __syncthreads();
        // sYt: 64 rows x 8 float4, transposed scatter (conflict-free: 4q+rr)
        #pragma unroll
        for (int n = 0; n < 2; n++) {
            int idx = n * 256 + tid;
            int rr = idx >> 3, q = idx & 7;
            float4 y4 = *(const float4*)&dgs[(size_t)(r0 + rr) * NN + j0 + 4 * q];
            sYt[4 * q + 0][rr] = y4.x;
            sYt[4 * q + 1][rr] = y4.y;
            sYt[4 * q + 2][rr] = y4.z;
            sYt[4 * q + 3][rr] = y4.w;
        }
        // sBu: H0[i0:i0+64][j0:j0+32], transposed scatter
        #pragma unroll
        for (int n = 0; n < 2; n++) {
            int idx = n * 256 + tid;
            int ii = idx >> 3, q = idx & 7;
            float4 h4 = *(const float4*)&H0g[(size_t)(i0 + ii) * NN + j0 + 4 * q];
            sBu[4 * q + 0][ii] = h4.x;
            sBu[4 * q + 1][ii] = h4.y;
            sBu[4 * q + 2][ii] = h4.z;
            sBu[4 * q + 3][ii] = h4.w;
        }
        // sBv: H0[j0:j0+32][i0:i0+64], direct float4 store
        #pragma unroll
        for (int n = 0; n < 2; n++) {
            int idx = n * 256 + tid;
            int jj = idx >> 4, q = idx & 15;
            float4 h4 = *(const float4*)&H0g[(size_t)(j0 + jj) * NN + i0 + 4 * q];
            *(float4*)&sBv[jj][4 * q] = h4;
        }
        __syncthreads();

        #pragma unroll 4
        for (int jj = 0; jj < 32; jj++) {
            float4 y4 = *(const float4*)&sYt[jj][rgi * 4];
            ulonglong2 bu = *(const ulonglong2*)&sBu[jj][cgi * 4];
            ulonglong2 bv = *(const ulonglong2*)&sBv[jj][cgi * 4];
            u64 y2[4] = {pack2(y4.x, y4.x), pack2(y4.y, y4.y),
                         pack2(y4.z, y4.z), pack2(y4.w, y4.w)};
            #pragma unroll
            for (int r = 0; r < 4; r++) {
                aU[r][0] = fma2(y2[r], bu.x, aU[r][0]);
                aU[r][1] = fma2(y2[r], bu.y, aU[r][1]);
                aV[r][0] = fma2(y2[r], bv.x, aV[r][0]);
                aV[r][1] = fma2(y2[r], bv.y, aV[r][1]);
            }
        }
    }

    // Write back: rows r0 + rgi*4 + rr, cols i0 + cgi*4 .. +3
    #pragma unroll
    for (int rr = 0; rr < 4; rr++) {
        size_t off = (size_t)(r0 + rgi * 4 + rr) * NN + i0 + cgi * 4;
        float4 uo, vo;
        unpack2(aU[rr][0], uo.x, uo.y);
        unpack2(aU[rr][1], uo.z, uo.w);
        unpack2(aV[rr][0], vo.x, vo.y);
        unpack2(aV[rr][1], vo.z, vo.w);
        *(float4*)&g_U0[off] = uo;
        *(float4*)&g_V0[off] = vo;
    }
}

// ---------------- K2: ks — per-pair scalar recursion + factor vectors ----------------
__global__ void __launch_bounds__(192)
ks_kernel(const float* __restrict__ steps, const float* __restrict__ dgs)
{
    __shared__ float sS[TT][NN], sY[TT][NN], sU0[TT][NN], sV0[TT][NN];
    __shared__ float sG1[TT][TT], sW[TT][TT];
    __shared__ float sCU[TT][TT], sCV[TT][TT], sB[TT][TT];
    __shared__ float sC1[TT], sC2[TT];

    const int tid = threadIdx.x;
    const int be  = blockIdx.x;

    for (int idx = tid; idx < TT * NN / 4; idx += 192) {
        int e = idx * 4;
        int k = e / NN, j = e % NN;
        size_t roff = (size_t)(k * BE + be) * NN + j;   // t-major rows
        *(float4*)&sS[k][j]  = *(const float4*)&steps[roff];
        *(float4*)&sY[k][j]  = *(const float4*)&dgs[roff];
        *(float4*)&sU0[k][j] = *(const float4*)&g_U0[roff];
        *(float4*)&sV0[k][j] = *(const float4*)&g_V0[roff];
    }
    __syncthreads();

    // Grams: G1 = S Y^T, W = V0 Y^T  (2x2 cells per thread, 72 threads)
    if (tid < 72) {
        int which = tid / 36;
        int cell  = tid % 36;
        int k0 = (cell / 6) * 2, t0 = (cell % 6) * 2;
        const float (*P)[NN] = which ? sV0 : sS;
        float a00 = 0.f, a01 = 0.f, a10 = 0.f, a11 = 0.f;
        for (int j = 0; j < NN; j += 4) {
            float4 p0 = *(const float4*)&P[k0][j];
            float4 p1 = *(const float4*)&P[k0 + 1][j];
            float4 q0 = *(const float4*)&sY[t0][j];
            float4 q1 = *(const float4*)&sY[t0 + 1][j];
            a00 += p0.x * q0.x + p0.y * q0.y + p0.z * q0.z + p0.w * q0.w;
            a01 += p0.x * q1.x + p0.y * q1.y + p0.z * q1.z + p0.w * q1.w;
            a10 += p1.x * q0.x + p1.y * q0.y + p1.z * q0.z + p1.w * q0.w;
            a11 += p1.x * q1.x + p1.y * q1.y + p1.z * q1.z + p1.w * q1.w;
        }
        float (*G)[TT] = which ? sW : sG1;
        G[k0][t0] = a00;     G[k0][t0 + 1] = a01;
        G[k0 + 1][t0] = a10; G[k0 + 1][t0 + 1] = a11;
    }
    __syncthreads();

    // Warp-0 scalar recursion, lane = column t
    if (tid < 32) {
        const int t = (tid < TT) ? tid : (TT - 1);
        float G1c[TT], Wc[TT], Wr[TT];
        float d2c[TT], d3c[TT];
        float c1v[TT], c2v[TT];
        float cuL[TT], cvL[TT], bL[TT];
        #pragma unroll
        for (int m = 0; m < TT; m++) {
            G1c[m] = sG1[m][t];
            Wc[m]  = sW[m][t];
            Wr[m]  = sW[t][m];
            cuL[m] = 0.f; cvL[m] = 0.f; bL[m] = 0.f;
        }
        #pragma unroll
        for (int k = 0; k < TT; k++) {
            if (k > 0) {
                const int m = k - 1;
                cuL[m] = c1v[m] * G1c[m] - c2v[m] * d2c[m];
                cvL[m] = c1v[m] * G1c[m] - c2v[m] * d3c[m];
                bL[m]  = -c2v[m] * G1c[m];
            }
            float x2 = Wc[k], x3 = Wr[k];
            #pragma unroll
            for (int m = 0; m < TT - 1; m++) {
                if (m < k) {
                    float cvk = __shfl_sync(0xFFFFFFFFu, cvL[m], k);
                    float cuk = __shfl_sync(0xFFFFFFFFu, cuL[m], k);
                    float bk  = __shfl_sync(0xFFFFFFFFu, bL[m],  k);
                    x2 += cvk * G1c[m] + bk * d2c[m];
                    x3 += cuk * G1c[m] + bk * d3c[m];
                }
            }
            d2c[k] = x2;
            d3c[k] = x3;
            float yHy  = __shfl_sync(0xFFFFFFFFu, x3, k);
            float sdot = __shfl_sync(0xFFFFFFFFu, G1c[k], k);
            float ic = (sdot != 0.0f) ? (1.0f / sdot) : 0.0f;
            c2v[k] = ic;
            c1v[k] = (sdot + yHy) * ic * ic;
        }
        if (tid < TT) {
            #pragma unroll
            for (int m = 0; m < TT - 1; m++) {
                sCU[m][t] = cuL[m];
                sCV[m][t] = cvL[m];
                sB[m][t]  = bL[m];
            }
        }
        if (tid == 0) {
            #pragma unroll
            for (int m = 0; m < TT; m++) { sC1[m] = c1v[m]; sC2[m] = c2v[m]; }
        }
    }
    __syncthreads();

    // Barrier-free per-element rebuild of u_t, v_t; emit A, Un (be-major)
    {
        const int i = tid;
        float s[TT], u[TT], v[TT];
        #pragma unroll
        for (int k = 0; k < TT; k++) {
            s[k] = sS[k][i];
            u[k] = sU0[k][i];
            v[k] = sV0[k][i];
        }
        #pragma unroll
        for (int t = 0; t < TT; t++) {
            #pragma unroll
            for (int k = 0; k < TT - 1; k++) {
                if (k < t) {
                    float bb = sB[k][t];
                    u[t] += sCU[k][t] * s[k] + bb * u[k];
                    v[t] += sCV[k][t] * s[k] + bb * v[k];
                }
            }
            float c1 = sC1[t], c2 = sC2[t];
            g_A [(size_t)(be * TT + t) * NN + i] = c1 * s[t] - c2 * v[t];
            g_Un[(size_t)(be * TT + t) * NN + i] = -c2 * u[t];
        }
    }
}

// ---------------- K3: ke — rank-24 epilogue GEMM ----------------
// grid = 256 pairs * 3 row-blocks (64 rows); 192 threads; 8x8 f32x2 tiles.
// cg = tid>>3 (8 lanes broadcast one column address), rg = tid&7.
__global__ void __launch_bounds__(192)
ke_kernel(const float* __restrict__ H0g,
          const float* __restrict__ steps,
          float* __restrict__ out)
{
    __shared__ float sA[TT][NN];
    __shared__ float sS[TT][NN];
    __shared__ float sUn[TT][64];
    const int tid  = threadIdx.x;
    const int be   = blockIdx.x / 3;
    const int rblk = (blockIdx.x % 3) * 64;

    for (int idx = tid; idx < TT * NN / 4; idx += 192) {
        int e = idx * 4;
        int k = e / NN, j = e % NN;
        *(float4*)&sA[k][j] = *(const float4*)&g_A[(size_t)(be * TT + k) * NN + j];
        *(float4*)&sS[k][j] = *(const float4*)&steps[(size_t)(k * BE + be) * NN + j];
    }
    {
        int e = tid * 4;               // TT*64/4 = 192 float4 loads, 1/thread
        int k = e / 64, r = e % 64;
        *(float4*)&sUn[k][r] = *(const float4*)&g_Un[(size_t)(be * TT + k) * NN + rblk + r];
    }
    __syncthreads();

    const int cg = tid >> 3, rg = tid & 7;
    const int c0  = cg * 8;
    const int lr0 = rg * 8;
    const int grow = rblk + lr0;
    float* ob = out + (size_t)be * NN * NN;

    u64 acc[8][4];
    #pragma unroll
    for (int r = 0; r < 8; r++) {
        ulonglong2 h01 = *(const ulonglong2*)&H0g[(size_t)(grow + r) * NN + c0];
        ulonglong2 h23 = *(const ulonglong2*)&H0g[(size_t)(grow + r) * NN + c0 + 4];
        acc[r][0] = h01.x; acc[r][1] = h01.y; acc[r][2] = h23.x; acc[r][3] = h23.y;
    }
    #pragma unroll
    for (int k = 0; k < TT; k++) {
        ulonglong2 a01 = *(ulonglong2*)&sA[k][c0];
        ulonglong2 a23 = *(ulonglong2*)&sA[k][c0 + 4];
        ulonglong2 s01 = *(ulonglong2*)&sS[k][c0];
        ulonglong2 s23 = *(ulonglong2*)&sS[k][c0 + 4];
        u64 av[4] = {a01.x, a01.y, a23.x, a23.y};
        u64 sv[4] = {s01.x, s01.y, s23.x, s23.y};
        float4 sr0 = *(float4*)&sS[k][grow];
        float4 sr1 = *(float4*)&sS[k][grow + 4];
        float4 ur0 = *(float4*)&sUn[k][lr0];
        float4 ur1 = *(float4*)&sUn[k][lr0 + 4];
        float srow[8] = {sr0.x, sr0.y, sr0.z, sr0.w, sr1.x, sr1.y, sr1.z, sr1.w};
        float urow[8] = {ur0.x, ur0.y, ur0.z, ur0.w, ur1.x, ur1.y, ur1.z, ur1.w};
        #pragma unroll
        for (int r = 0; r < 8; r++) {
            u64 s2 = pack2(srow[r], srow[r]);
            u64 u2 = pack2(urow[r], urow[r]);
            #pragma unroll
            for (int c = 0; c < 4; c++) {
                acc[r][c] = fma2(s2, av[c], acc[r][c]);
                acc[r][c] = fma2(u2, sv[c], acc[r][c]);
            }
        }
    }
    #pragma unroll
    for (int r = 0; r < 8; r++) {
        *(ulonglong2*)&ob[(size_t)(grow + r) * NN + c0] =
            make_ulonglong2(acc[r][0], acc[r][1]);
        *(ulonglong2*)&ob[(size_t)(grow + r) * NN + c0 + 4] =
            make_ulonglong2(acc[r][2], acc[r][3]);
    }
}

extern "C" void kernel_launch(void* const* d_in, const int* in_sizes, int n_in,
                              void* d_out, int out_size) {
    const float* H0    = (const float*)d_in[0];   // inv_hessian [192,192]
    const float* steps = (const float*)d_in[1];   // [12,8,32,192]
    const float* dgs   = (const float*)d_in[2];   // [12,8,32,192]
    float* out = (float*)d_out;                   // [8,32,192,192]

    kz_kernel<<<144, 256>>>(H0, dgs);
    ks_kernel<<<BE, 192>>>(steps, dgs);
    ke_kernel<<<BE * 3, 192>>>(H0, steps, out);
}